// round 4
// baseline (speedup 1.0000x reference)
#include <cuda_runtime.h>
#include <cuda_fp16.h>
#include <cstdint>

// Sinkhorn, linear domain, fp16-compressed kernel matrix, self-synchronizing
// column normalization (no separate combine kernel):
//   K = valid ? fp16(exp(m)) : 0          (device-global scratch, built fused
//                                          with Sinkhorn step 1 since v0 = 1)
//   10x: { u_i = 1/sum_j K_ij v_j ; v_j = 1/sum_i K_ij u_i }
//   out = valid ? u_i * exp(m_ij) * v_j : 0   (fp32 exp recompute)
// B=64, N=1024, M=1024, tau=1.

#define BB 64
#define NN 1024
#define MM 1024

__device__ __half g_K[(size_t)BB * NN * MM];   // 128 MB scratch
__device__ float  g_u[BB * NN];
__device__ float  g_v[BB * MM];
__device__ float  g_s[BB * MM];                // col-sum accumulator (self-zeroing)
__device__ int    g_cnt[BB];                   // per-batch block retirement counter

// ---------------------------------------------------------------------------
// Shared epilogue: stage per-warp column accumulators in smem, one atomicAdd
// per column, ticket-retire; last block of the batch inverts s -> v, re-zeros
// s, resets the counter. Leaves global state clean for graph replay.
// ---------------------------------------------------------------------------
__device__ __forceinline__ void col_epilogue(int b, int nr, int nc, int npass,
                                             int w, int lane, const float* acc) {
    __shared__ float sm[8 * 1024];
    __shared__ int ticket;
    #pragma unroll
    for (int p = 0; p < 8; p++) {
        *reinterpret_cast<float4*>(&sm[w * 1024 + p * 128 + lane * 4]) =
            make_float4(acc[p * 4 + 0], acc[p * 4 + 1], acc[p * 4 + 2], acc[p * 4 + 3]);
    }
    __syncthreads();
    int t = threadIdx.x;
    int jmax = npass << 7;
    #pragma unroll
    for (int r = 0; r < 4; r++) {
        int j = r * 256 + t;
        if (j < jmax) {
            float s = 0.f;
            #pragma unroll
            for (int ww = 0; ww < 8; ww++) s += sm[ww * 1024 + j];
            atomicAdd(&g_s[(b << 10) + j], s);
        }
    }
    __threadfence();
    __syncthreads();
    if (t == 0) ticket = atomicAdd(&g_cnt[b], 1);
    __syncthreads();
    int nblk = (nr + 31) >> 5;
    if (ticket == nblk - 1) {
        __threadfence();   // acquire: all batches' g_s atomics visible
        #pragma unroll
        for (int r = 0; r < 4; r++) {
            int idx = (b << 10) + r * 256 + t;
            int j = r * 256 + t;
            float s = __ldcg(&g_s[idx]);
            g_s[idx] = 0.f;
            g_v[idx] = (j < nc && s > 0.f) ? (1.0f / s) : 0.f;
        }
        if (t == 0) g_cnt[b] = 0;
    }
}

// ---------------------------------------------------------------------------
// Build + Sinkhorn step 1 (v0 = 1): block = 32 rows of one batch, 8 warps x
// 4 rows. Computes exp(m) masked, writes fp16 K (padded col tiles), row sums
// -> u1, column accumulation -> v1 via last-block retire.
// grid = (32, 64), block = 256.
// ---------------------------------------------------------------------------
__global__ void __launch_bounds__(256) build_fused_kernel(const float* __restrict__ m,
                                                          const int* __restrict__ nrows,
                                                          const int* __restrict__ ncols) {
    int b  = blockIdx.y;
    int nr = nrows[b];
    int nc = ncols[b];
    int i0 = blockIdx.x * 32;
    if (i0 >= nr || nc == 0) return;
    int npass = (nc + 127) >> 7;

    int lane = threadIdx.x & 31;
    int w    = threadIdx.x >> 5;

    float acc[32];
    #pragma unroll
    for (int k = 0; k < 32; k++) acc[k] = 0.f;

    const float* mb = m + ((size_t)b << 20);
    __half*      Kb = g_K + ((size_t)b << 20);

    #pragma unroll
    for (int q = 0; q < 4; q++) {
        int i = i0 + w * 4 + q;
        if (i < nr) {
            const float* mrow = mb + ((size_t)i << 10);
            __half*      krow = Kb + ((size_t)i << 10);
            uint2 kk[8];
            float s0 = 0.f, s1 = 0.f, s2 = 0.f, s3 = 0.f;
            #pragma unroll
            for (int p = 0; p < 8; p++) {
                if (p < npass) {
                    int j = p * 128 + lane * 4;
                    float4 mv = *reinterpret_cast<const float4*>(mrow + j);
                    float e0 = (j + 0 < nc) ? __expf(mv.x) : 0.f;
                    float e1 = (j + 1 < nc) ? __expf(mv.y) : 0.f;
                    float e2 = (j + 2 < nc) ? __expf(mv.z) : 0.f;
                    float e3 = (j + 3 < nc) ? __expf(mv.w) : 0.f;
                    __half2 h0 = __floats2half2_rn(e0, e1);
                    __half2 h1 = __floats2half2_rn(e2, e3);
                    kk[p].x = *reinterpret_cast<uint32_t*>(&h0);
                    kk[p].y = *reinterpret_cast<uint32_t*>(&h1);
                    *reinterpret_cast<uint2*>(krow + j) = kk[p];
                } else {
                    kk[p] = make_uint2(0u, 0u);
                }
                float2 f0 = __half22float2(*reinterpret_cast<__half2*>(&kk[p].x));
                float2 f1 = __half22float2(*reinterpret_cast<__half2*>(&kk[p].y));
                s0 += f0.x; s1 += f0.y; s2 += f1.x; s3 += f1.y;   // v0 = 1
            }
            float sum = (s0 + s1) + (s2 + s3);
            #pragma unroll
            for (int o = 16; o; o >>= 1) sum += __shfl_xor_sync(0xffffffffu, sum, o);
            float u = (sum > 0.f) ? (1.0f / sum) : 0.f;
            if (lane == 0) g_u[(b << 10) + i] = u;
            #pragma unroll
            for (int p = 0; p < 8; p++) {
                float2 f0 = __half22float2(*reinterpret_cast<__half2*>(&kk[p].x));
                float2 f1 = __half22float2(*reinterpret_cast<__half2*>(&kk[p].y));
                acc[p * 4 + 0] = fmaf(f0.x, u, acc[p * 4 + 0]);
                acc[p * 4 + 1] = fmaf(f0.y, u, acc[p * 4 + 1]);
                acc[p * 4 + 2] = fmaf(f1.x, u, acc[p * 4 + 2]);
                acc[p * 4 + 3] = fmaf(f1.y, u, acc[p * 4 + 3]);
            }
        }
    }
    col_epilogue(b, nr, nc, npass, w, lane, acc);
}

// ---------------------------------------------------------------------------
// Fused Sinkhorn step: row normalize (u from current v) + column accumulate,
// K read once in fp16; v inverted by last retiring block.
// grid = (32, 64), block = 256.
// ---------------------------------------------------------------------------
__global__ void __launch_bounds__(256) fused_pass_kernel(const int* __restrict__ nrows,
                                                         const int* __restrict__ ncols) {
    int b  = blockIdx.y;
    int nr = nrows[b];
    int nc = ncols[b];
    int i0 = blockIdx.x * 32;
    if (i0 >= nr || nc == 0) return;
    int npass = (nc + 127) >> 7;

    int lane = threadIdx.x & 31;
    int w    = threadIdx.x >> 5;

    const float* vrow = g_v + (b << 10);
    float4 vr[8];
    #pragma unroll
    for (int p = 0; p < 8; p++)
        vr[p] = *reinterpret_cast<const float4*>(vrow + p * 128 + lane * 4);

    float acc[32];
    #pragma unroll
    for (int k = 0; k < 32; k++) acc[k] = 0.f;

    const __half* Kb = g_K + ((size_t)b << 20);

    #pragma unroll
    for (int q = 0; q < 4; q++) {
        int i = i0 + w * 4 + q;
        if (i < nr) {
            const __half* krow = Kb + ((size_t)i << 10);
            uint2 kk[8];
            float s0 = 0.f, s1 = 0.f, s2 = 0.f, s3 = 0.f;
            #pragma unroll
            for (int p = 0; p < 8; p++) {
                if (p < npass)
                    kk[p] = *reinterpret_cast<const uint2*>(krow + p * 128 + lane * 4);
                else
                    kk[p] = make_uint2(0u, 0u);
                float2 f0 = __half22float2(*reinterpret_cast<__half2*>(&kk[p].x));
                float2 f1 = __half22float2(*reinterpret_cast<__half2*>(&kk[p].y));
                s0 = fmaf(f0.x, vr[p].x, s0);
                s1 = fmaf(f0.y, vr[p].y, s1);
                s2 = fmaf(f1.x, vr[p].z, s2);
                s3 = fmaf(f1.y, vr[p].w, s3);
            }
            float sum = (s0 + s1) + (s2 + s3);
            #pragma unroll
            for (int o = 16; o; o >>= 1) sum += __shfl_xor_sync(0xffffffffu, sum, o);
            float u = (sum > 0.f) ? (1.0f / sum) : 0.f;
            if (lane == 0) g_u[(b << 10) + i] = u;
            #pragma unroll
            for (int p = 0; p < 8; p++) {
                float2 f0 = __half22float2(*reinterpret_cast<__half2*>(&kk[p].x));
                float2 f1 = __half22float2(*reinterpret_cast<__half2*>(&kk[p].y));
                acc[p * 4 + 0] = fmaf(f0.x, u, acc[p * 4 + 0]);
                acc[p * 4 + 1] = fmaf(f0.y, u, acc[p * 4 + 1]);
                acc[p * 4 + 2] = fmaf(f1.x, u, acc[p * 4 + 2]);
                acc[p * 4 + 3] = fmaf(f1.y, u, acc[p * 4 + 3]);
            }
        }
    }
    col_epilogue(b, nr, nc, npass, w, lane, acc);
}

// ---------------------------------------------------------------------------
// Final: out = valid ? u_i * exp(m_ij) * v_j : 0 — exp recomputed in fp32.
// grid = 4096, block = 256, 16 float4/thread (full 256 MB write).
// ---------------------------------------------------------------------------
__global__ void final_kernel(const float* __restrict__ m,
                             const int* __restrict__ nrows,
                             const int* __restrict__ ncols,
                             float* __restrict__ out) {
    int b   = blockIdx.x >> 6;
    int sub = blockIdx.x & 63;
    int nr = nrows[b];
    int nc = ncols[b];
    const float* mb = m + ((size_t)b << 20);
    float*       ob = out + ((size_t)b << 20);

    #pragma unroll
    for (int k = 0; k < 16; k++) {
        int q = sub * 4096 + k * 256 + threadIdx.x;  // float4 index in batch
        int i = q >> 8;
        int j = (q & 255) << 2;
        float4 o;
        if (i >= nr || j >= nc) {
            o = make_float4(0.f, 0.f, 0.f, 0.f);
        } else {
            float4 mm = *reinterpret_cast<const float4*>(mb + ((size_t)q << 2));
            float  u  = g_u[(b << 10) + i];
            float4 vv = *reinterpret_cast<const float4*>(g_v + (b << 10) + j);
            // v_j == 0 for j >= nc, so tail elements of a boundary float4
            // are zeroed automatically (exp(m) is finite).
            o.x = __expf(mm.x) * u * vv.x;
            o.y = __expf(mm.y) * u * vv.y;
            o.z = __expf(mm.z) * u * vv.z;
            o.w = __expf(mm.w) * u * vv.w;
        }
        *reinterpret_cast<float4*>(ob + ((size_t)q << 2)) = o;
    }
}

extern "C" void kernel_launch(void* const* d_in, const int* in_sizes, int n_in,
                              void* d_out, int out_size) {
    const float* m     = (const float*)d_in[0];
    const int*   nrows = (const int*)d_in[1];
    const int*   ncols = (const int*)d_in[2];
    float* out = (float*)d_out;

    build_fused_kernel<<<dim3(32, 64), 256>>>(m, nrows, ncols);   // step 1
    for (int t = 0; t < 9; t++)                                   // steps 2..10
        fused_pass_kernel<<<dim3(32, 64), 256>>>(nrows, ncols);
    final_kernel<<<4096, 256>>>(m, nrows, ncols, out);
}

// round 5
// speedup vs baseline: 1.1665x; 1.1665x over previous
#include <cuda_runtime.h>
#include <cuda_fp16.h>
#include <cstdint>

// Sinkhorn, linear domain, fp16-compressed kernel matrix, stage-buffered
// column sums (no per-iteration sync kernel, no fences):
//   K = valid ? fp16(exp(m)) : 0      (built fused with Sinkhorn step 1, v0=1)
//   step t: u_i = 1 / sum_j K_ij * inv(sb[t-1]_j) ; sb[t]_j += sum_i K_ij u_i
//   out = valid ? u_i * exp(m_ij) * inv(sb[9]_j) : 0   (fp32 exp recompute)
// B=64, N=1024, M=1024, tau=1, 10 steps. inv(s) = s>0 ? 1/s : 0 (s==0 exactly
// for invalid columns since only zeros are ever accumulated there).

#define BB 64
#define NN 1024
#define MM 1024
#define NSTAGE 10

__device__ __half g_K[(size_t)BB * NN * MM];     // 128 MB scratch
__device__ float  g_u[BB * NN];
__device__ float  g_sb[NSTAGE][BB * MM];         // per-stage col-sum buffers

// ---------------------------------------------------------------------------
// Zero all stage buffers (once per replay). 2.56 MB. grid=160, block=256.
// ---------------------------------------------------------------------------
__global__ void init_kernel() {
    float4* p = reinterpret_cast<float4*>(&g_sb[0][0]);
    int idx = blockIdx.x * blockDim.x + threadIdx.x;
    const int total = NSTAGE * BB * MM / 4;   // 163840 float4
    #pragma unroll
    for (int r = 0; r < 4; r++) {
        int q = idx + r * 40960;
        if (q < total) p[q] = make_float4(0.f, 0.f, 0.f, 0.f);
    }
}

// ---------------------------------------------------------------------------
// Epilogue: stage per-warp column accumulators in smem, sum across warps,
// one atomicAdd per column into s_out. No fence, no ticket — the kernel
// boundary is the sync.
// ---------------------------------------------------------------------------
__device__ __forceinline__ void col_epilogue(int b, int npass, int w, int lane,
                                             const float* acc, float* s_out) {
    __shared__ float sm[8 * 1024];
    #pragma unroll
    for (int p = 0; p < 8; p++) {
        *reinterpret_cast<float4*>(&sm[w * 1024 + p * 128 + lane * 4]) =
            make_float4(acc[p * 4 + 0], acc[p * 4 + 1], acc[p * 4 + 2], acc[p * 4 + 3]);
    }
    __syncthreads();
    int t = threadIdx.x;
    int jmax = npass << 7;
    #pragma unroll
    for (int r = 0; r < 4; r++) {
        int j = r * 256 + t;
        if (j < jmax) {
            float s = 0.f;
            #pragma unroll
            for (int ww = 0; ww < 8; ww++) s += sm[ww * 1024 + j];
            atomicAdd(&s_out[(b << 10) + j], s);
        }
    }
}

// ---------------------------------------------------------------------------
// Build + Sinkhorn step 1 (v0 = 1): block = 32 rows x 8 warps x 4 rows.
// exp(m) masked -> fp16 K (padded col tiles), row sums -> u1, col partials
// -> g_sb[0]. grid = (32, 64), block = 256.
// ---------------------------------------------------------------------------
__global__ void __launch_bounds__(256) build_fused_kernel(const float* __restrict__ m,
                                                          const int* __restrict__ nrows,
                                                          const int* __restrict__ ncols) {
    int b  = blockIdx.y;
    int nr = nrows[b];
    int nc = ncols[b];
    int i0 = blockIdx.x * 32;
    if (i0 >= nr || nc == 0) return;
    int npass = (nc + 127) >> 7;

    int lane = threadIdx.x & 31;
    int w    = threadIdx.x >> 5;

    float acc[32];
    #pragma unroll
    for (int k = 0; k < 32; k++) acc[k] = 0.f;

    const float* mb = m + ((size_t)b << 20);
    __half*      Kb = g_K + ((size_t)b << 20);

    #pragma unroll
    for (int q = 0; q < 4; q++) {
        int i = i0 + w * 4 + q;
        if (i < nr) {
            const float* mrow = mb + ((size_t)i << 10);
            __half*      krow = Kb + ((size_t)i << 10);
            uint2 kk[8];
            float s0 = 0.f, s1 = 0.f, s2 = 0.f, s3 = 0.f;
            #pragma unroll
            for (int p = 0; p < 8; p++) {
                if (p < npass) {
                    int j = p * 128 + lane * 4;
                    float4 mv = *reinterpret_cast<const float4*>(mrow + j);
                    float e0 = (j + 0 < nc) ? __expf(mv.x) : 0.f;
                    float e1 = (j + 1 < nc) ? __expf(mv.y) : 0.f;
                    float e2 = (j + 2 < nc) ? __expf(mv.z) : 0.f;
                    float e3 = (j + 3 < nc) ? __expf(mv.w) : 0.f;
                    __half2 h0 = __floats2half2_rn(e0, e1);
                    __half2 h1 = __floats2half2_rn(e2, e3);
                    kk[p].x = *reinterpret_cast<uint32_t*>(&h0);
                    kk[p].y = *reinterpret_cast<uint32_t*>(&h1);
                    *reinterpret_cast<uint2*>(krow + j) = kk[p];
                } else {
                    kk[p] = make_uint2(0u, 0u);
                }
                float2 f0 = __half22float2(*reinterpret_cast<__half2*>(&kk[p].x));
                float2 f1 = __half22float2(*reinterpret_cast<__half2*>(&kk[p].y));
                s0 += f0.x; s1 += f0.y; s2 += f1.x; s3 += f1.y;   // v0 = 1
            }
            float sum = (s0 + s1) + (s2 + s3);
            #pragma unroll
            for (int o = 16; o; o >>= 1) sum += __shfl_xor_sync(0xffffffffu, sum, o);
            float u = (sum > 0.f) ? __fdividef(1.0f, sum) : 0.f;
            if (lane == 0) g_u[(b << 10) + i] = u;
            #pragma unroll
            for (int p = 0; p < 8; p++) {
                float2 f0 = __half22float2(*reinterpret_cast<__half2*>(&kk[p].x));
                float2 f1 = __half22float2(*reinterpret_cast<__half2*>(&kk[p].y));
                acc[p * 4 + 0] = fmaf(f0.x, u, acc[p * 4 + 0]);
                acc[p * 4 + 1] = fmaf(f0.y, u, acc[p * 4 + 1]);
                acc[p * 4 + 2] = fmaf(f1.x, u, acc[p * 4 + 2]);
                acc[p * 4 + 3] = fmaf(f1.y, u, acc[p * 4 + 3]);
            }
        }
    }
    col_epilogue(b, npass, w, lane, acc, &g_sb[0][0]);
}

// ---------------------------------------------------------------------------
// Fused Sinkhorn step `stage` (1..9): reads col sums g_sb[stage-1], inverts
// on the fly (v = s>0 ? 1/s : 0), row normalize -> u, col partials ->
// g_sb[stage]. grid = (32, 64), block = 256.
// ---------------------------------------------------------------------------
__global__ void __launch_bounds__(256) fused_pass_kernel(const int* __restrict__ nrows,
                                                         const int* __restrict__ ncols,
                                                         int stage) {
    int b  = blockIdx.y;
    int nr = nrows[b];
    int nc = ncols[b];
    int i0 = blockIdx.x * 32;
    if (i0 >= nr || nc == 0) return;
    int npass = (nc + 127) >> 7;

    int lane = threadIdx.x & 31;
    int w    = threadIdx.x >> 5;

    const float* s_in = &g_sb[stage - 1][b << 10];
    float4 vr[8];
    #pragma unroll
    for (int p = 0; p < 8; p++) {
        float4 s4 = *reinterpret_cast<const float4*>(s_in + p * 128 + lane * 4);
        vr[p].x = (s4.x > 0.f) ? __fdividef(1.0f, s4.x) : 0.f;
        vr[p].y = (s4.y > 0.f) ? __fdividef(1.0f, s4.y) : 0.f;
        vr[p].z = (s4.z > 0.f) ? __fdividef(1.0f, s4.z) : 0.f;
        vr[p].w = (s4.w > 0.f) ? __fdividef(1.0f, s4.w) : 0.f;
    }

    float acc[32];
    #pragma unroll
    for (int k = 0; k < 32; k++) acc[k] = 0.f;

    const __half* Kb = g_K + ((size_t)b << 20);

    #pragma unroll
    for (int q = 0; q < 4; q++) {
        int i = i0 + w * 4 + q;
        if (i < nr) {
            const __half* krow = Kb + ((size_t)i << 10);
            uint2 kk[8];
            float s0 = 0.f, s1 = 0.f, s2 = 0.f, s3 = 0.f;
            #pragma unroll
            for (int p = 0; p < 8; p++) {
                if (p < npass)
                    kk[p] = *reinterpret_cast<const uint2*>(krow + p * 128 + lane * 4);
                else
                    kk[p] = make_uint2(0u, 0u);
                float2 f0 = __half22float2(*reinterpret_cast<__half2*>(&kk[p].x));
                float2 f1 = __half22float2(*reinterpret_cast<__half2*>(&kk[p].y));
                s0 = fmaf(f0.x, vr[p].x, s0);
                s1 = fmaf(f0.y, vr[p].y, s1);
                s2 = fmaf(f1.x, vr[p].z, s2);
                s3 = fmaf(f1.y, vr[p].w, s3);
            }
            float sum = (s0 + s1) + (s2 + s3);
            #pragma unroll
            for (int o = 16; o; o >>= 1) sum += __shfl_xor_sync(0xffffffffu, sum, o);
            float u = (sum > 0.f) ? __fdividef(1.0f, sum) : 0.f;
            if (lane == 0) g_u[(b << 10) + i] = u;
            #pragma unroll
            for (int p = 0; p < 8; p++) {
                float2 f0 = __half22float2(*reinterpret_cast<__half2*>(&kk[p].x));
                float2 f1 = __half22float2(*reinterpret_cast<__half2*>(&kk[p].y));
                acc[p * 4 + 0] = fmaf(f0.x, u, acc[p * 4 + 0]);
                acc[p * 4 + 1] = fmaf(f0.y, u, acc[p * 4 + 1]);
                acc[p * 4 + 2] = fmaf(f1.x, u, acc[p * 4 + 2]);
                acc[p * 4 + 3] = fmaf(f1.y, u, acc[p * 4 + 3]);
            }
        }
    }
    col_epilogue(b, npass, w, lane, acc, &g_sb[stage][0]);
}

// ---------------------------------------------------------------------------
// Final: out = valid ? u_i * exp(m_ij) * inv(sb[9]_j) : 0 — fp32 exp.
// grid = 4096, block = 256, 16 float4/thread (full 256 MB write).
// ---------------------------------------------------------------------------
__global__ void final_kernel(const float* __restrict__ m,
                             const int* __restrict__ nrows,
                             const int* __restrict__ ncols,
                             float* __restrict__ out) {
    int b   = blockIdx.x >> 6;
    int sub = blockIdx.x & 63;
    int nr = nrows[b];
    int nc = ncols[b];
    const float* mb = m + ((size_t)b << 20);
    float*       ob = out + ((size_t)b << 20);
    const float* sb = &g_sb[NSTAGE - 1][b << 10];

    #pragma unroll
    for (int k = 0; k < 16; k++) {
        int q = sub * 4096 + k * 256 + threadIdx.x;  // float4 index in batch
        int i = q >> 8;
        int j = (q & 255) << 2;
        float4 o;
        if (i >= nr || j >= nc) {
            o = make_float4(0.f, 0.f, 0.f, 0.f);
        } else {
            float4 mm = *reinterpret_cast<const float4*>(mb + ((size_t)q << 2));
            float  u  = g_u[(b << 10) + i];
            float4 s4 = *reinterpret_cast<const float4*>(sb + j);
            float vx = (s4.x > 0.f) ? __fdividef(1.0f, s4.x) : 0.f;
            float vy = (s4.y > 0.f) ? __fdividef(1.0f, s4.y) : 0.f;
            float vz = (s4.z > 0.f) ? __fdividef(1.0f, s4.z) : 0.f;
            float vw = (s4.w > 0.f) ? __fdividef(1.0f, s4.w) : 0.f;
            // s==0 exactly for j >= nc, so tail elements of a boundary
            // float4 are zeroed automatically (exp(m) is finite).
            o.x = __expf(mm.x) * u * vx;
            o.y = __expf(mm.y) * u * vy;
            o.z = __expf(mm.z) * u * vz;
            o.w = __expf(mm.w) * u * vw;
        }
        *reinterpret_cast<float4*>(ob + ((size_t)q << 2)) = o;
    }
}

extern "C" void kernel_launch(void* const* d_in, const int* in_sizes, int n_in,
                              void* d_out, int out_size) {
    const float* m     = (const float*)d_in[0];
    const int*   nrows = (const int*)d_in[1];
    const int*   ncols = (const int*)d_in[2];
    float* out = (float*)d_out;

    init_kernel<<<160, 256>>>();                                   // zero stage bufs
    build_fused_kernel<<<dim3(32, 64), 256>>>(m, nrows, ncols);    // step 1
    for (int t = 1; t <= 9; t++)                                   // steps 2..10
        fused_pass_kernel<<<dim3(32, 64), 256>>>(nrows, ncols, t);
    final_kernel<<<4096, 256>>>(m, nrows, ncols, out);
}

// round 6
// speedup vs baseline: 1.4711x; 1.2611x over previous
#include <cuda_runtime.h>
#include <cuda_fp16.h>
#include <cstdint>

// Sinkhorn, linear domain, fp16-compressed kernel matrix, stage-buffered
// column sums (no per-iteration sync kernel, no fences):
//   K = valid ? fp16(exp(m)) : 0      (built fused with Sinkhorn step 1, v0=1)
//   step t: u_i = 1 / sum_j K_ij * inv(sb[t-1]_j) ; sb[t]_j += sum_i K_ij u_i
//   out = valid ? u_i * exp(m_ij) * inv(sb[9]_j) : 0   (fp32 exp recompute)
// B=64, N=1024, M=1024, tau=1, 10 steps. inv(s) = s>0 ? 1/s : 0 (s==0 exactly
// for invalid columns since only zeros are ever accumulated there).
//
// fused_pass is two-phase per warp row-group to keep register state small
// (no 32-wide column accumulator array): phase 1 streams K -> row sums -> u,
// phase 2 re-reads the warp's own 8 KB K tile (L1/L2-hot) and stages per-tile
// column partials directly to smem.

#define BB 64
#define NN 1024
#define MM 1024
#define NSTAGE 10

__device__ __half g_K[(size_t)BB * NN * MM];     // 128 MB scratch
__device__ float  g_u[BB * NN];
__device__ float  g_sb[NSTAGE][BB * MM];         // per-stage col-sum buffers

// ---------------------------------------------------------------------------
// Zero all stage buffers (once per replay). 2.56 MB. grid=160, block=256.
// ---------------------------------------------------------------------------
__global__ void init_kernel() {
    float4* p = reinterpret_cast<float4*>(&g_sb[0][0]);
    int idx = blockIdx.x * blockDim.x + threadIdx.x;
    const int total = NSTAGE * BB * MM / 4;   // 163840 float4
    #pragma unroll
    for (int r = 0; r < 4; r++) {
        int q = idx + r * 40960;
        if (q < total) p[q] = make_float4(0.f, 0.f, 0.f, 0.f);
    }
}

// ---------------------------------------------------------------------------
// Build + Sinkhorn step 1 (v0 = 1): block = 32 rows x 8 warps x 4 rows.
// exp(m) masked -> fp16 K (padded col tiles), row sums -> u1, col partials
// -> g_sb[0]. grid = (32, 64), block = 256.  (Single-phase; runs once.)
// ---------------------------------------------------------------------------
__global__ void __launch_bounds__(256) build_fused_kernel(const float* __restrict__ m,
                                                          const int* __restrict__ nrows,
                                                          const int* __restrict__ ncols) {
    int b  = blockIdx.y;
    int nr = nrows[b];
    int nc = ncols[b];
    int i0 = blockIdx.x * 32;
    if (i0 >= nr || nc == 0) return;
    int npass = (nc + 127) >> 7;

    int lane = threadIdx.x & 31;
    int w    = threadIdx.x >> 5;

    float acc[32];
    #pragma unroll
    for (int k = 0; k < 32; k++) acc[k] = 0.f;

    const float* mb = m + ((size_t)b << 20);
    __half*      Kb = g_K + ((size_t)b << 20);

    #pragma unroll
    for (int q = 0; q < 4; q++) {
        int i = i0 + w * 4 + q;
        if (i < nr) {
            const float* mrow = mb + ((size_t)i << 10);
            __half*      krow = Kb + ((size_t)i << 10);
            uint2 kk[8];
            float s0 = 0.f, s1 = 0.f, s2 = 0.f, s3 = 0.f;
            #pragma unroll
            for (int p = 0; p < 8; p++) {
                if (p < npass) {
                    int j = p * 128 + lane * 4;
                    float4 mv = *reinterpret_cast<const float4*>(mrow + j);
                    float e0 = (j + 0 < nc) ? __expf(mv.x) : 0.f;
                    float e1 = (j + 1 < nc) ? __expf(mv.y) : 0.f;
                    float e2 = (j + 2 < nc) ? __expf(mv.z) : 0.f;
                    float e3 = (j + 3 < nc) ? __expf(mv.w) : 0.f;
                    __half2 h0 = __floats2half2_rn(e0, e1);
                    __half2 h1 = __floats2half2_rn(e2, e3);
                    kk[p].x = *reinterpret_cast<uint32_t*>(&h0);
                    kk[p].y = *reinterpret_cast<uint32_t*>(&h1);
                    *reinterpret_cast<uint2*>(krow + j) = kk[p];
                } else {
                    kk[p] = make_uint2(0u, 0u);
                }
                float2 f0 = __half22float2(*reinterpret_cast<__half2*>(&kk[p].x));
                float2 f1 = __half22float2(*reinterpret_cast<__half2*>(&kk[p].y));
                s0 += f0.x; s1 += f0.y; s2 += f1.x; s3 += f1.y;   // v0 = 1
            }
            float sum = (s0 + s1) + (s2 + s3);
            #pragma unroll
            for (int o = 16; o; o >>= 1) sum += __shfl_xor_sync(0xffffffffu, sum, o);
            float u = (sum > 0.f) ? __fdividef(1.0f, sum) : 0.f;
            if (lane == 0) g_u[(b << 10) + i] = u;
            #pragma unroll
            for (int p = 0; p < 8; p++) {
                float2 f0 = __half22float2(*reinterpret_cast<__half2*>(&kk[p].x));
                float2 f1 = __half22float2(*reinterpret_cast<__half2*>(&kk[p].y));
                acc[p * 4 + 0] = fmaf(f0.x, u, acc[p * 4 + 0]);
                acc[p * 4 + 1] = fmaf(f0.y, u, acc[p * 4 + 1]);
                acc[p * 4 + 2] = fmaf(f1.x, u, acc[p * 4 + 2]);
                acc[p * 4 + 3] = fmaf(f1.y, u, acc[p * 4 + 3]);
            }
        }
    }
    // epilogue (inline; same as fused pass)
    __shared__ float sm[8 * 1024];
    #pragma unroll
    for (int p = 0; p < 8; p++) {
        *reinterpret_cast<float4*>(&sm[w * 1024 + p * 128 + lane * 4]) =
            make_float4(acc[p * 4 + 0], acc[p * 4 + 1], acc[p * 4 + 2], acc[p * 4 + 3]);
    }
    __syncthreads();
    int t = threadIdx.x;
    int jmax = npass << 7;
    #pragma unroll
    for (int r = 0; r < 4; r++) {
        int j = r * 256 + t;
        if (j < jmax) {
            float s = 0.f;
            #pragma unroll
            for (int ww = 0; ww < 8; ww++) s += sm[ww * 1024 + j];
            atomicAdd(&g_sb[0][(b << 10) + j], s);
        }
    }
}

// ---------------------------------------------------------------------------
// Fused Sinkhorn step `stage` (1..9), two-phase low-register version:
//   prologue: invert sb[stage-1] into smem v (4 KB)
//   per warp (4 rows): phase 1 stream K tiles, dot with smem v -> row sums
//                      -> u[4] (shuffle-reduced, broadcast to all lanes)
//                      phase 2 re-read same tiles, fma with u, stage acc[4]
//                      per tile into per-warp smem row
//   epilogue: cross-warp smem sum, one atomicAdd per column into sb[stage].
// grid = (32, 64), block = 256.
// ---------------------------------------------------------------------------
__global__ void __launch_bounds__(256, 4) fused_pass_kernel(const int* __restrict__ nrows,
                                                            const int* __restrict__ ncols,
                                                            int stage) {
    int b  = blockIdx.y;
    int nr = nrows[b];
    int nc = ncols[b];
    int i0 = blockIdx.x * 32;
    if (i0 >= nr || nc == 0) return;
    int npass = (nc + 127) >> 7;

    int lane = threadIdx.x & 31;
    int w    = threadIdx.x >> 5;
    int t    = threadIdx.x;

    __shared__ float sv[1024];        // inverted column potentials
    __shared__ float sm[8 * 1024];    // per-warp column partial staging

    // invert s -> v into smem (s==0 for invalid cols -> v=0)
    {
        const float* s_in = &g_sb[stage - 1][b << 10];
        float4 s4 = *reinterpret_cast<const float4*>(s_in + t * 4);
        float4 v4;
        v4.x = (s4.x > 0.f) ? __fdividef(1.0f, s4.x) : 0.f;
        v4.y = (s4.y > 0.f) ? __fdividef(1.0f, s4.y) : 0.f;
        v4.z = (s4.z > 0.f) ? __fdividef(1.0f, s4.z) : 0.f;
        v4.w = (s4.w > 0.f) ? __fdividef(1.0f, s4.w) : 0.f;
        *reinterpret_cast<float4*>(&sv[t * 4]) = v4;
    }
    __syncthreads();

    const __half* Kb = g_K + ((size_t)b << 20);
    int ibase = i0 + w * 4;
    int nrow  = min(4, nr - ibase);   // valid rows in this warp's group (may be <=0)

    // ---- phase 1: row sums ----
    float sums[4] = {0.f, 0.f, 0.f, 0.f};
    for (int p = 0; p < npass; p++) {
        float4 v4 = *reinterpret_cast<const float4*>(&sv[p * 128 + lane * 4]);
        #pragma unroll
        for (int q = 0; q < 4; q++) {
            if (q < nrow) {
                uint2 kk = *reinterpret_cast<const uint2*>(
                    Kb + ((size_t)(ibase + q) << 10) + p * 128 + lane * 4);
                float2 f0 = __half22float2(*reinterpret_cast<__half2*>(&kk.x));
                float2 f1 = __half22float2(*reinterpret_cast<__half2*>(&kk.y));
                float s = fmaf(f0.x, v4.x, fmaf(f0.y, v4.y,
                          fmaf(f1.x, v4.z, f1.y * v4.w)));
                sums[q] += s;
            }
        }
    }
    float u[4];
    #pragma unroll
    for (int q = 0; q < 4; q++) {
        float s = sums[q];
        #pragma unroll
        for (int o = 16; o; o >>= 1) s += __shfl_xor_sync(0xffffffffu, s, o);
        u[q] = (s > 0.f) ? __fdividef(1.0f, s) : 0.f;
        if (lane == 0 && q < nrow) g_u[(b << 10) + ibase + q] = u[q];
    }

    // ---- phase 2: column partials (re-read warp's own 8 KB tile, L1/L2-hot) ----
    for (int p = 0; p < npass; p++) {
        float a0 = 0.f, a1 = 0.f, a2 = 0.f, a3 = 0.f;
        #pragma unroll
        for (int q = 0; q < 4; q++) {
            if (q < nrow) {
                uint2 kk = *reinterpret_cast<const uint2*>(
                    Kb + ((size_t)(ibase + q) << 10) + p * 128 + lane * 4);
                float2 f0 = __half22float2(*reinterpret_cast<__half2*>(&kk.x));
                float2 f1 = __half22float2(*reinterpret_cast<__half2*>(&kk.y));
                a0 = fmaf(f0.x, u[q], a0);
                a1 = fmaf(f0.y, u[q], a1);
                a2 = fmaf(f1.x, u[q], a2);
                a3 = fmaf(f1.y, u[q], a3);
            }
        }
        *reinterpret_cast<float4*>(&sm[w * 1024 + p * 128 + lane * 4]) =
            make_float4(a0, a1, a2, a3);
    }
    __syncthreads();

    // ---- epilogue: cross-warp sum + global atomic ----
    int jmax = npass << 7;
    float* s_out = &g_sb[stage][b << 10];
    #pragma unroll
    for (int r = 0; r < 4; r++) {
        int j = r * 256 + t;
        if (j < jmax) {
            float s = 0.f;
            #pragma unroll
            for (int ww = 0; ww < 8; ww++) s += sm[ww * 1024 + j];
            atomicAdd(&s_out[j], s);
        }
    }
}

// ---------------------------------------------------------------------------
// Final: out = valid ? u_i * exp(m_ij) * inv(sb[9]_j) : 0 — fp32 exp.
// grid = 4096, block = 256, 16 float4/thread (full 256 MB write).
// ---------------------------------------------------------------------------
__global__ void final_kernel(const float* __restrict__ m,
                             const int* __restrict__ nrows,
                             const int* __restrict__ ncols,
                             float* __restrict__ out) {
    int b   = blockIdx.x >> 6;
    int sub = blockIdx.x & 63;
    int nr = nrows[b];
    int nc = ncols[b];
    const float* mb = m + ((size_t)b << 20);
    float*       ob = out + ((size_t)b << 20);
    const float* sb = &g_sb[NSTAGE - 1][b << 10];

    #pragma unroll
    for (int k = 0; k < 16; k++) {
        int q = sub * 4096 + k * 256 + threadIdx.x;  // float4 index in batch
        int i = q >> 8;
        int j = (q & 255) << 2;
        float4 o;
        if (i >= nr || j >= nc) {
            o = make_float4(0.f, 0.f, 0.f, 0.f);
        } else {
            float4 mm = *reinterpret_cast<const float4*>(mb + ((size_t)q << 2));
            float  u  = g_u[(b << 10) + i];
            float4 s4 = *reinterpret_cast<const float4*>(sb + j);
            float vx = (s4.x > 0.f) ? __fdividef(1.0f, s4.x) : 0.f;
            float vy = (s4.y > 0.f) ? __fdividef(1.0f, s4.y) : 0.f;
            float vz = (s4.z > 0.f) ? __fdividef(1.0f, s4.z) : 0.f;
            float vw = (s4.w > 0.f) ? __fdividef(1.0f, s4.w) : 0.f;
            // s==0 exactly for j >= nc, so tail elements of a boundary
            // float4 are zeroed automatically (exp(m) is finite).
            o.x = __expf(mm.x) * u * vx;
            o.y = __expf(mm.y) * u * vy;
            o.z = __expf(mm.z) * u * vz;
            o.w = __expf(mm.w) * u * vw;
        }
        *reinterpret_cast<float4*>(ob + ((size_t)q << 2)) = o;
    }
}

extern "C" void kernel_launch(void* const* d_in, const int* in_sizes, int n_in,
                              void* d_out, int out_size) {
    const float* m     = (const float*)d_in[0];
    const int*   nrows = (const int*)d_in[1];
    const int*   ncols = (const int*)d_in[2];
    float* out = (float*)d_out;

    init_kernel<<<160, 256>>>();                                   // zero stage bufs
    build_fused_kernel<<<dim3(32, 64), 256>>>(m, nrows, ncols);    // step 1
    for (int t = 1; t <= 9; t++)                                   // steps 2..10
        fused_pass_kernel<<<dim3(32, 64), 256>>>(nrows, ncols, t);
    final_kernel<<<4096, 256>>>(m, nrows, ncols, out);
}